// round 2
// baseline (speedup 1.0000x reference)
#include <cuda_runtime.h>

// DeltaLoss: loss = mean_p [ 0.5*(LSE_row(p) + LSE_col(p)) - mma[p,p] ]
// mma = 100 * (normalized pair-diffs of txtf) @ (normalized pair-diffs of imgf)^T
// Fixed-shift LSE with SHIFT=30: entries <= 100 -> exp(x-30) <= e^70 (no overflow);
// every row/col sum >= exp(diag-30) >= e^-49 (no subnormal -> no lg2.approx flush).

#define NN    96
#define D     512
#define P     9120            // 96*95 ordered pairs
#define PPAD  9216            // 72 * 128
#define BM    128
#define BN    128
#define BK    8
#define TM    8
#define TN    8
#define GT    (PPAD / BM)     // 72 tiles per dim
#define SHIFT 30.0f

// ---- scratch (static device globals; no allocation APIs) ----
__device__ float g_td[(size_t)PPAD * D];   // normalized txt pair diffs (padded rows = 0)
__device__ float g_im[(size_t)PPAD * D];   // normalized img pair diffs
__device__ float g_rowSum[PPAD];           // sum_q exp(mma[p,q] - SHIFT)
__device__ float g_colSum[PPAD];           // sum_p exp(mma[p,q] - SHIFT)
__device__ float g_diag[PPAD];             // mma[p,p]

__device__ __forceinline__ float block_reduce_sum_256(float v, float* red) {
    #pragma unroll
    for (int o = 16; o > 0; o >>= 1)
        v += __shfl_xor_sync(0xffffffffu, v, o);
    const int t = threadIdx.x;
    __syncthreads();                 // protect red reuse across calls
    if ((t & 31) == 0) red[t >> 5] = v;
    __syncthreads();
    float r = 0.f;
    #pragma unroll
    for (int w = 0; w < 8; ++w) r += red[w];
    return r;                        // every thread gets the total
}

__global__ void zero_sums_kernel() {
    const int t = blockIdx.x * blockDim.x + threadIdx.x;
    if (t < PPAD) { g_rowSum[t] = 0.f; g_colSum[t] = 0.f; }
}

// One block per pair p (blocks [P, PPAD) zero the padding rows).
// 256 threads, 2 elements each (D=512).
__global__ __launch_bounds__(256) void pairdiff_kernel(const float* __restrict__ txtf,
                                                       const float* __restrict__ imgf) {
    __shared__ float red[8];
    const int p = blockIdx.x;
    const int t = threadIdx.x;

    if (p >= P) {   // zero padding rows so the GEMM can load unguarded
        g_td[(size_t)p * D + t]       = 0.f;
        g_td[(size_t)p * D + t + 256] = 0.f;
        g_im[(size_t)p * D + t]       = 0.f;
        g_im[(size_t)p * D + t + 256] = 0.f;
        if (t == 0) g_diag[p] = 0.f;
        return;
    }

    // pair enumeration matching reference row-major meshgrid with i != j
    const int i  = p / (NN - 1);
    const int jr = p - i * (NN - 1);
    const int j  = jr + (jr >= i ? 1 : 0);

    const int e0 = t, e1 = t + 256;
    float td0 = txtf[i * D + e0] - txtf[j * D + e0];
    float td1 = txtf[i * D + e1] - txtf[j * D + e1];
    float im0 = imgf[i * D + e0] - imgf[j * D + e0];
    float im1 = imgf[i * D + e1] - imgf[j * D + e1];

    const float sst = block_reduce_sum_256(td0 * td0 + td1 * td1, red);
    const float ssi = block_reduce_sum_256(im0 * im0 + im1 * im1, red);
    const float st = 1.0f / (sqrtf(sst) + 1e-8f);   // reference: x / (||x|| + eps)
    const float si = 1.0f / (sqrtf(ssi) + 1e-8f);
    td0 *= st; td1 *= st; im0 *= si; im1 *= si;

    g_td[(size_t)p * D + e0] = td0;
    g_td[(size_t)p * D + e1] = td1;
    g_im[(size_t)p * D + e0] = im0;
    g_im[(size_t)p * D + e1] = im1;

    const float dt = block_reduce_sum_256(td0 * im0 + td1 * im1, red);
    if (t == 0) g_diag[p] = 100.0f * dt;
}

// C = 100 * td @ im^T, fused epilogue: e = exp(C - SHIFT), reduce rows/cols.
// 128x128 tile, BK=8, 8x8 per thread, 256 threads.
__global__ __launch_bounds__(256) void gemm_lse_kernel() {
    __shared__ float As[BK][BM];
    __shared__ float Bs[BK][BN];
    __shared__ float rowAcc[BM];
    __shared__ float colAcc[BN];

    const int t  = threadIdx.x;
    const int tx = t & 15;          // 16 thread cols
    const int ty = t >> 4;          // 16 thread rows
    const int lr = t >> 1;          // load row 0..127
    const int lk = (t & 1) * 4;     // load k offset 0 or 4

    const float* __restrict__ ag = g_td + (size_t)blockIdx.y * BM * D + (size_t)lr * D + lk;
    const float* __restrict__ bg = g_im + (size_t)blockIdx.x * BN * D + (size_t)lr * D + lk;

    if (t < BM) { rowAcc[t] = 0.f; colAcc[t] = 0.f; }

    float acc[TM][TN];
    #pragma unroll
    for (int m = 0; m < TM; ++m)
        #pragma unroll
        for (int n = 0; n < TN; ++n) acc[m][n] = 0.f;

    for (int ks = 0; ks < D; ks += BK) {
        const float4 av = *(const float4*)(ag + ks);
        const float4 bv = *(const float4*)(bg + ks);
        __syncthreads();
        As[lk + 0][lr] = av.x; As[lk + 1][lr] = av.y;
        As[lk + 2][lr] = av.z; As[lk + 3][lr] = av.w;
        Bs[lk + 0][lr] = bv.x; Bs[lk + 1][lr] = bv.y;
        Bs[lk + 2][lr] = bv.z; Bs[lk + 3][lr] = bv.w;
        __syncthreads();
        #pragma unroll
        for (int k = 0; k < BK; ++k) {
            float a[TM], b[TN];
            *(float4*)&a[0] = *(const float4*)&As[k][ty * TM];
            *(float4*)&a[4] = *(const float4*)&As[k][ty * TM + 4];
            *(float4*)&b[0] = *(const float4*)&Bs[k][tx * TN];
            *(float4*)&b[4] = *(const float4*)&Bs[k][tx * TN + 4];
            #pragma unroll
            for (int m = 0; m < TM; ++m)
                #pragma unroll
                for (int n = 0; n < TN; ++n)
                    acc[m][n] = fmaf(a[m], b[n], acc[m][n]);
        }
    }

    // epilogue: exp(100*dot - SHIFT), masked row/col partial sums
    const int grow0 = blockIdx.y * BM + ty * TM;
    const int gcol0 = blockIdx.x * BN + tx * TN;

    float rs[TM], cs[TN];
    #pragma unroll
    for (int m = 0; m < TM; ++m) rs[m] = 0.f;
    #pragma unroll
    for (int n = 0; n < TN; ++n) cs[n] = 0.f;

    #pragma unroll
    for (int m = 0; m < TM; ++m) {
        const bool rv = (grow0 + m) < P;
        #pragma unroll
        for (int n = 0; n < TN; ++n) {
            const bool cv = (gcol0 + n) < P;
            float e = __expf(fmaf(100.0f, acc[m][n], -SHIFT));
            e = (rv && cv) ? e : 0.0f;
            rs[m] += e;
            cs[n] += e;
        }
    }

    __syncthreads();
    #pragma unroll
    for (int m = 0; m < TM; ++m) atomicAdd(&rowAcc[ty * TM + m], rs[m]);
    #pragma unroll
    for (int n = 0; n < TN; ++n) atomicAdd(&colAcc[tx * TN + n], cs[n]);
    __syncthreads();

    if (t < BM) {
        const int gr = blockIdx.y * BM + t;
        const int gc = blockIdx.x * BN + t;
        if (gr < P) atomicAdd(&g_rowSum[gr], rowAcc[t]);
        if (gc < P) atomicAdd(&g_colSum[gc], colAcc[t]);
    }
}

__global__ __launch_bounds__(256) void finalize_kernel(float* __restrict__ out) {
    __shared__ float red[8];
    const int t = threadIdx.x;
    float s = 0.f;
    for (int p = t; p < P; p += 256) {
        // LSE_row = SHIFT + log(rowSum), LSE_col = SHIFT + log(colSum)
        s += SHIFT + 0.5f * (logf(g_rowSum[p]) + logf(g_colSum[p])) - g_diag[p];
    }
    const float tot = block_reduce_sum_256(s, red);
    if (t == 0) out[0] = tot / (float)P;
}

extern "C" void kernel_launch(void* const* d_in, const int* in_sizes, int n_in,
                              void* d_out, int out_size) {
    const float* txtf = (const float*)d_in[0];
    const float* imgf = (const float*)d_in[1];
    (void)in_sizes; (void)n_in; (void)out_size;

    zero_sums_kernel<<<(PPAD + 255) / 256, 256>>>();
    pairdiff_kernel<<<PPAD, 256>>>(txtf, imgf);
    gemm_lse_kernel<<<dim3(GT, GT), 256>>>();
    finalize_kernel<<<1, 256>>>((float*)d_out);
}

// round 4
// speedup vs baseline: 5.9943x; 5.9943x over previous
#include <cuda_runtime.h>
#include <cuda_bf16.h>
#include <cstdint>

// DeltaLoss via bf16 mma.sync GEMM (arch-agnostic tensor path; tcgen05 is
// rejected because the harness builds through compute_103 non-'a' virtual arch).
// C = 100 * td_hat @ im_hat^T; streaming LSE with fixed SHIFT=30:
//   entries <= 100 -> exp(x-30) <= e^70 (no overflow)
//   every row/col sum >= exp(diag-30) >= e^-49 (stays normal fp32)

#define NN    96
#define D     512
#define P     9120
#define PPAD  9216
#define BM    128
#define BN    128
#define BK    32
#define NKB   (D / BK)       // 16
#define SHIFT 30.0f

// ---- scratch ----
__device__ __nv_bfloat16 g_tdh[(size_t)PPAD * D];
__device__ __nv_bfloat16 g_imh[(size_t)PPAD * D];
__device__ float g_rowSum[PPAD];
__device__ float g_colSum[PPAD];
__device__ float g_diag[PPAD];

__device__ __forceinline__ uint32_t smem_u32(const void* p) {
    uint32_t a;
    asm("{ .reg .u64 t; cvta.to.shared.u64 t, %1; cvt.u32.u64 %0, t; }" : "=r"(a) : "l"(p));
    return a;
}

#define LDSM_X4(r0, r1, r2, r3, addr) \
    asm volatile("ldmatrix.sync.aligned.m8n8.x4.shared.b16 {%0,%1,%2,%3}, [%4];" \
        : "=r"(r0), "=r"(r1), "=r"(r2), "=r"(r3) : "r"(addr))

#define MMA16816(c, a, b0, b1) \
    asm volatile("mma.sync.aligned.m16n8k16.row.col.f32.bf16.bf16.f32 " \
        "{%0,%1,%2,%3}, {%4,%5,%6,%7}, {%8,%9}, {%0,%1,%2,%3};" \
        : "+f"((c)[0]), "+f"((c)[1]), "+f"((c)[2]), "+f"((c)[3]) \
        : "r"((a)[0]), "r"((a)[1]), "r"((a)[2]), "r"((a)[3]), "r"(b0), "r"(b1))

__device__ __forceinline__ float block_reduce_sum_256(float v, float* red) {
    #pragma unroll
    for (int o = 16; o > 0; o >>= 1) v += __shfl_xor_sync(0xffffffffu, v, o);
    const int t = threadIdx.x;
    __syncthreads();
    if ((t & 31) == 0) red[t >> 5] = v;
    __syncthreads();
    float r = 0.f;
    #pragma unroll
    for (int w = 0; w < 8; ++w) r += red[w];
    return r;
}

__global__ void zero_sums_kernel(float* __restrict__ out) {
    const int t = blockIdx.x * blockDim.x + threadIdx.x;
    if (t < PPAD) { g_rowSum[t] = 0.f; g_colSum[t] = 0.f; }
    if (t == 0) out[0] = 0.f;
}

// One block per pair p (blocks [P, PPAD) zero padding rows). 256 thr, 2 elems each.
__global__ __launch_bounds__(256) void pairdiff_kernel(const float* __restrict__ txtf,
                                                       const float* __restrict__ imgf) {
    __shared__ float red[8];
    const int p = blockIdx.x;
    const int t = threadIdx.x;
    if (p >= P) {
        const __nv_bfloat16 z = __float2bfloat16(0.f);
        g_tdh[(size_t)p * D + t] = z;       g_tdh[(size_t)p * D + t + 256] = z;
        g_imh[(size_t)p * D + t] = z;       g_imh[(size_t)p * D + t + 256] = z;
        if (t == 0) g_diag[p] = 0.f;
        return;
    }
    const int i  = p / (NN - 1);
    const int jr = p - i * (NN - 1);
    const int j  = jr + (jr >= i ? 1 : 0);

    const int e0 = t, e1 = t + 256;
    float td0 = txtf[i * D + e0] - txtf[j * D + e0];
    float td1 = txtf[i * D + e1] - txtf[j * D + e1];
    float im0 = imgf[i * D + e0] - imgf[j * D + e0];
    float im1 = imgf[i * D + e1] - imgf[j * D + e1];

    const float sst = block_reduce_sum_256(td0 * td0 + td1 * td1, red);
    const float ssi = block_reduce_sum_256(im0 * im0 + im1 * im1, red);
    const float st = 1.0f / (sqrtf(sst) + 1e-8f);
    const float si = 1.0f / (sqrtf(ssi) + 1e-8f);
    td0 *= st; td1 *= st; im0 *= si; im1 *= si;

    g_tdh[(size_t)p * D + e0] = __float2bfloat16(td0);
    g_tdh[(size_t)p * D + e1] = __float2bfloat16(td1);
    g_imh[(size_t)p * D + e0] = __float2bfloat16(im0);
    g_imh[(size_t)p * D + e1] = __float2bfloat16(im1);

    const float dt = block_reduce_sum_256(td0 * im0 + td1 * im1, red);
    if (t == 0) g_diag[p] = 100.0f * dt;
}

// exp(100*acc - 30) on the FMA pipe (poly exp2, no MUFU)
__device__ __forceinline__ float fast_exp_shift(float acc) {
    float t = fmaf(acc, 144.26950408889634f, -43.280851226668903f); // *log2(e)
    t = fmaxf(t, -125.0f);
    const float r = t + 12582912.0f;             // round-to-nearest int
    const float n = r - 12582912.0f;
    const float f = t - n;
    float pl = 0.0013333558146428443f;
    pl = fmaf(pl, f, 0.009618129107628477f);
    pl = fmaf(pl, f, 0.05550410866482158f);
    pl = fmaf(pl, f, 0.2402265069591007f);
    pl = fmaf(pl, f, 0.6931471805599453f);
    pl = fmaf(pl, f, 1.0f);
    const uint32_t sb = ((__float_as_uint(r) + (127u - 0x4B400000u)) << 23);
    return pl * __uint_as_float(sb);
}

// 128x128 tile, BK=32, 8 warps (4x2), warp tile 32x64 via m16n8k16 bf16 HMMA.
// Smem XOR swizzle: 16B chunk c at row r lives at chunk (c ^ ((r>>1)&3)).
__global__ void __launch_bounds__(256) gemm_lse_mma() {
    __shared__ __align__(128) __nv_bfloat16 smA[2][BM * BK];
    __shared__ __align__(128) __nv_bfloat16 smB[2][BN * BK];
    __shared__ float rowAcc[BM];
    __shared__ float colAcc[BN];

    const int tid  = threadIdx.x;
    const int lane = tid & 31;
    const int wid  = tid >> 5;
    const int wm   = wid >> 1;        // 0..3
    const int wn   = wid & 1;         // 0..1
    const int bx = blockIdx.x, by = blockIdx.y;

    if (tid < BM) { rowAcc[tid] = 0.f; colAcc[tid] = 0.f; }

    const uint32_t aBase = smem_u32(&smA[0][0]);
    const uint32_t bBase = smem_u32(&smB[0][0]);

    // cp.async assignments: 512 16B-chunks per tile, 2 per thread per tile
    uint32_t dstA[2], dstB[2];
    const __nv_bfloat16* srcA[2];
    const __nv_bfloat16* srcB[2];
    #pragma unroll
    for (int it = 0; it < 2; ++it) {
        const int c = tid + it * 256, row = c >> 2, cc = c & 3;
        const int sw = cc ^ ((row >> 1) & 3);
        dstA[it] = aBase + row * 64 + sw * 16;
        dstB[it] = bBase + row * 64 + sw * 16;
        srcA[it] = g_tdh + (size_t)(by * BM + row) * D + cc * 8;
        srcB[it] = g_imh + (size_t)(bx * BN + row) * D + cc * 8;
    }

    // ldmatrix addresses (stage-0; add s*8192 for stage 1)
    uint32_t aLd[2][2], bLd[2][4];   // [ks][mt], [ks][pair]
    {
        const int rA  = wm * 32 + (lane & 7) + (lane & 8);
        const int cAk = (lane >> 4);
        const int rB  = wn * 64 + (lane & 7) + ((lane & 16) >> 1);
        const int cBk = (lane >> 3) & 1;
        #pragma unroll
        for (int ks = 0; ks < 2; ++ks) {
            #pragma unroll
            for (int mt = 0; mt < 2; ++mt) {
                const int row = rA + mt * 16, ch = ks * 2 + cAk;
                aLd[ks][mt] = aBase + row * 64 + ((ch ^ ((row >> 1) & 3)) * 16);
            }
            #pragma unroll
            for (int pr = 0; pr < 4; ++pr) {
                const int row = rB + pr * 16, ch = ks * 2 + cBk;
                bLd[ks][pr] = bBase + row * 64 + ((ch ^ ((row >> 1) & 3)) * 16);
            }
        }
    }

    float acc[2][8][4];
    #pragma unroll
    for (int mt = 0; mt < 2; ++mt)
        #pragma unroll
        for (int nt = 0; nt < 8; ++nt)
            #pragma unroll
            for (int k = 0; k < 4; ++k) acc[mt][nt][k] = 0.f;

    // prologue
    #pragma unroll
    for (int kb0 = 0; kb0 < 2; ++kb0) {
        #pragma unroll
        for (int it = 0; it < 2; ++it) {
            asm volatile("cp.async.cg.shared.global [%0], [%1], 16;"
                :: "r"(dstA[it] + kb0 * 8192u), "l"(srcA[it] + kb0 * BK));
            asm volatile("cp.async.cg.shared.global [%0], [%1], 16;"
                :: "r"(dstB[it] + kb0 * 8192u), "l"(srcB[it] + kb0 * BK));
        }
        asm volatile("cp.async.commit_group;" ::: "memory");
    }

    #pragma unroll
    for (int kb = 0; kb < NKB; ++kb) {
        const int s = kb & 1;
        const uint32_t so = (uint32_t)s * 8192u;
        if (kb < NKB - 2) asm volatile("cp.async.wait_group 1;" ::: "memory");
        else              asm volatile("cp.async.wait_group 0;" ::: "memory");
        __syncthreads();

        uint32_t af[2][2][4], bf[2][4][4];
        #pragma unroll
        for (int ks = 0; ks < 2; ++ks) {
            #pragma unroll
            for (int mt = 0; mt < 2; ++mt)
                LDSM_X4(af[ks][mt][0], af[ks][mt][1], af[ks][mt][2], af[ks][mt][3],
                        aLd[ks][mt] + so);
            #pragma unroll
            for (int pr = 0; pr < 4; ++pr)
                LDSM_X4(bf[ks][pr][0], bf[ks][pr][1], bf[ks][pr][2], bf[ks][pr][3],
                        bLd[ks][pr] + so);
        }
        __syncthreads();                    // all reads of stage s done

        if (kb + 2 < NKB) {                 // refill stage s for kb+2
            #pragma unroll
            for (int it = 0; it < 2; ++it) {
                asm volatile("cp.async.cg.shared.global [%0], [%1], 16;"
                    :: "r"(dstA[it] + so), "l"(srcA[it] + (kb + 2) * BK));
                asm volatile("cp.async.cg.shared.global [%0], [%1], 16;"
                    :: "r"(dstB[it] + so), "l"(srcB[it] + (kb + 2) * BK));
            }
            asm volatile("cp.async.commit_group;" ::: "memory");
        }

        #pragma unroll
        for (int ks = 0; ks < 2; ++ks)
            #pragma unroll
            for (int mt = 0; mt < 2; ++mt)
                #pragma unroll
                for (int nt = 0; nt < 8; ++nt) {
                    const uint32_t b0 = bf[ks][nt >> 1][(nt & 1) * 2 + 0];
                    const uint32_t b1 = bf[ks][nt >> 1][(nt & 1) * 2 + 1];
                    MMA16816(acc[mt][nt], af[ks][mt], b0, b1);
                }
    }

    // ---- fused epilogue: exp + row/col reduce ----
    // C frag: c0,c1 = row lane/4, cols 2*(lane&3), +1 ; c2,c3 = row+8
    float rp[2][2];
    float cp[8][2];
    #pragma unroll
    for (int mt = 0; mt < 2; ++mt) { rp[mt][0] = 0.f; rp[mt][1] = 0.f; }
    #pragma unroll
    for (int nt = 0; nt < 8; ++nt) { cp[nt][0] = 0.f; cp[nt][1] = 0.f; }

    const int row0g = by * BM + wm * 32 + (lane >> 2);
    const int col0g = bx * BN + wn * 64 + (lane & 3) * 2;

    #pragma unroll
    for (int mt = 0; mt < 2; ++mt) {
        const int r0 = row0g + mt * 16;
        const bool ok0 = r0 < P, ok1 = (r0 + 8) < P;
        #pragma unroll
        for (int nt = 0; nt < 8; ++nt) {
            const int c0 = col0g + nt * 8;
            const bool okc0 = c0 < P, okc1 = (c0 + 1) < P;
            float e0 = fast_exp_shift(acc[mt][nt][0]); e0 = (ok0 && okc0) ? e0 : 0.f;
            float e1 = fast_exp_shift(acc[mt][nt][1]); e1 = (ok0 && okc1) ? e1 : 0.f;
            float e2 = fast_exp_shift(acc[mt][nt][2]); e2 = (ok1 && okc0) ? e2 : 0.f;
            float e3 = fast_exp_shift(acc[mt][nt][3]); e3 = (ok1 && okc1) ? e3 : 0.f;
            rp[mt][0] += e0 + e1;
            rp[mt][1] += e2 + e3;
            cp[nt][0] += e0 + e2;
            cp[nt][1] += e1 + e3;
        }
    }

    // row partials: reduce over the 4 lanes sharing a row (lane&3 varies)
    #pragma unroll
    for (int mt = 0; mt < 2; ++mt) {
        #pragma unroll
        for (int h = 0; h < 2; ++h) {
            float v = rp[mt][h];
            v += __shfl_xor_sync(0xffffffffu, v, 1);
            v += __shfl_xor_sync(0xffffffffu, v, 2);
            if ((lane & 3) == 0)
                atomicAdd(&rowAcc[wm * 32 + mt * 16 + (lane >> 2) + h * 8], v);
        }
    }
    // col partials: reduce over the 8 lanes sharing a col (lane>>2 varies)
    #pragma unroll
    for (int nt = 0; nt < 8; ++nt) {
        #pragma unroll
        for (int h = 0; h < 2; ++h) {
            float v = cp[nt][h];
            v += __shfl_xor_sync(0xffffffffu, v, 4);
            v += __shfl_xor_sync(0xffffffffu, v, 8);
            v += __shfl_xor_sync(0xffffffffu, v, 16);
            if (lane < 4)
                atomicAdd(&colAcc[wn * 64 + nt * 8 + lane * 2 + h], v);
        }
    }

    __syncthreads();
    if (tid < BM) {
        const int gr = by * BM + tid;
        const int gc = bx * BN + tid;
        if (gr < P) atomicAdd(&g_rowSum[gr], rowAcc[tid]);
        if (gc < P) atomicAdd(&g_colSum[gc], colAcc[tid]);
    }
}

__global__ __launch_bounds__(256) void finalize_kernel(float* __restrict__ out) {
    __shared__ float red[8];
    const int t = threadIdx.x;
    const int p0 = blockIdx.x * 256 + t;
    float s = 0.f;
    if (p0 < P)
        s = SHIFT + 0.5f * (logf(g_rowSum[p0]) + logf(g_colSum[p0])) - g_diag[p0];
    const float tot = block_reduce_sum_256(s, red);
    if (t == 0) atomicAdd(out, tot / (float)P);
}

extern "C" void kernel_launch(void* const* d_in, const int* in_sizes, int n_in,
                              void* d_out, int out_size) {
    const float* txtf = (const float*)d_in[0];
    const float* imgf = (const float*)d_in[1];
    (void)in_sizes; (void)n_in; (void)out_size;
    float* out = (float*)d_out;

    zero_sums_kernel<<<(PPAD + 255) / 256, 256>>>(out);
    pairdiff_kernel<<<PPAD, 256>>>(txtf, imgf);
    gemm_lse_mma<<<dim3(PPAD / BN, PPAD / BM), 256>>>();
    finalize_kernel<<<(P + 255) / 256, 256>>>(out);
}

// round 5
// speedup vs baseline: 18.5778x; 3.0993x over previous
#include <cuda_runtime.h>
#include <cuda_bf16.h>
#include <cstdint>

// DeltaLoss via bf16 mma.sync GEMM over the i<j HALF of the pair set.
// Antisymmetry: td(j,i) = -td(i,j), im(j,i) = -im(i,j)  =>
//   rowSum[(j,i)] = rowSum[(i,j)], colSum likewise, diag identical.
// Full-matrix row sum for p in S (i<j):
//   rowSum[p] = sum_{q in S} [exp(x_pq-30) + exp(-x_pq-30)]
// loss = mean_{p in S} [30 + 0.5*(log rowSum + log colSum) - diag].
// SHIFT=30: entries <= 100 -> e^70 max (no overflow); sums >= e^(diag-30) >= e^-49.

#define NN    96
#define D     512
#define P2    4560           // NN*(NN-1)/2 pairs with i<j
#define P2PAD 4608           // 36 * 128
#define BM    128
#define BN    128
#define BK    32
#define NKB   (D / BK)       // 16
#define SHIFT 30.0f

// ---- scratch ----
__device__ __nv_bfloat16 g_tdh[(size_t)P2PAD * D];
__device__ __nv_bfloat16 g_imh[(size_t)P2PAD * D];
__device__ float g_rowSum[P2PAD];
__device__ float g_colSum[P2PAD];
__device__ float g_diag[P2PAD];

__device__ __forceinline__ uint32_t smem_u32(const void* p) {
    uint32_t a;
    asm("{ .reg .u64 t; cvta.to.shared.u64 t, %1; cvt.u32.u64 %0, t; }" : "=r"(a) : "l"(p));
    return a;
}

#define LDSM_X4(r0, r1, r2, r3, addr) \
    asm volatile("ldmatrix.sync.aligned.m8n8.x4.shared.b16 {%0,%1,%2,%3}, [%4];" \
        : "=r"(r0), "=r"(r1), "=r"(r2), "=r"(r3) : "r"(addr))

#define MMA16816(c, a, b0, b1) \
    asm volatile("mma.sync.aligned.m16n8k16.row.col.f32.bf16.bf16.f32 " \
        "{%0,%1,%2,%3}, {%4,%5,%6,%7}, {%8,%9}, {%0,%1,%2,%3};" \
        : "+f"((c)[0]), "+f"((c)[1]), "+f"((c)[2]), "+f"((c)[3]) \
        : "r"((a)[0]), "r"((a)[1]), "r"((a)[2]), "r"((a)[3]), "r"(b0), "r"(b1))

__device__ __forceinline__ float block_reduce_sum_256(float v, float* red) {
    #pragma unroll
    for (int o = 16; o > 0; o >>= 1) v += __shfl_xor_sync(0xffffffffu, v, o);
    const int t = threadIdx.x;
    __syncthreads();
    if ((t & 31) == 0) red[t >> 5] = v;
    __syncthreads();
    float r = 0.f;
    #pragma unroll
    for (int w = 0; w < 8; ++w) r += red[w];
    return r;
}

// triangular index -> (i, j) with i < j, lexicographic
__device__ __forceinline__ void tri_ij(int p, int& i, int& j) {
    float pf = (float)p;
    int ii = (int)(((2.0f * NN - 1.0f)
             - sqrtf((2.0f * NN - 1.0f) * (2.0f * NN - 1.0f) - 8.0f * pf)) * 0.5f);
    if (ii < 0) ii = 0;
    while (ii > 0 && ii * (2 * NN - ii - 1) / 2 > p) --ii;
    while ((ii + 1) * (2 * NN - ii - 2) / 2 + (ii + 1) <= p &&
           (ii + 1) * (2 * NN - (ii + 1) - 1) / 2 <= p) ++ii;
    // (the second while uses offset(i) = i*(2*NN-i-1)/2)
    i = ii;
    j = ii + 1 + (p - ii * (2 * NN - ii - 1) / 2);
}

__global__ void zero_sums_kernel(float* __restrict__ out) {
    const int t = blockIdx.x * blockDim.x + threadIdx.x;
    if (t < P2PAD) { g_rowSum[t] = 0.f; g_colSum[t] = 0.f; }
    if (t == 0) out[0] = 0.f;
}

// One block per pair p in S (blocks [P2, P2PAD) zero padding rows).
__global__ __launch_bounds__(256) void pairdiff_kernel(const float* __restrict__ txtf,
                                                       const float* __restrict__ imgf) {
    __shared__ float red[8];
    const int p = blockIdx.x;
    const int t = threadIdx.x;
    if (p >= P2) {
        const __nv_bfloat16 z = __float2bfloat16(0.f);
        g_tdh[(size_t)p * D + t] = z;       g_tdh[(size_t)p * D + t + 256] = z;
        g_imh[(size_t)p * D + t] = z;       g_imh[(size_t)p * D + t + 256] = z;
        if (t == 0) g_diag[p] = 0.f;
        return;
    }
    int i, j;
    tri_ij(p, i, j);

    const int e0 = t, e1 = t + 256;
    float td0 = txtf[i * D + e0] - txtf[j * D + e0];
    float td1 = txtf[i * D + e1] - txtf[j * D + e1];
    float im0 = imgf[i * D + e0] - imgf[j * D + e0];
    float im1 = imgf[i * D + e1] - imgf[j * D + e1];

    const float sst = block_reduce_sum_256(td0 * td0 + td1 * td1, red);
    const float ssi = block_reduce_sum_256(im0 * im0 + im1 * im1, red);
    const float st = 1.0f / (sqrtf(sst) + 1e-8f);
    const float si = 1.0f / (sqrtf(ssi) + 1e-8f);
    td0 *= st; td1 *= st; im0 *= si; im1 *= si;

    g_tdh[(size_t)p * D + e0] = __float2bfloat16(td0);
    g_tdh[(size_t)p * D + e1] = __float2bfloat16(td1);
    g_imh[(size_t)p * D + e0] = __float2bfloat16(im0);
    g_imh[(size_t)p * D + e1] = __float2bfloat16(im1);

    const float dt = block_reduce_sum_256(td0 * im0 + td1 * im1, red);
    if (t == 0) g_diag[p] = 100.0f * dt;
}

// exp(s*100*acc - 30) on the FMA pipe (poly exp2, no MUFU)
__device__ __forceinline__ float fast_exp_shift(float acc, float scale) {
    float t = fmaf(acc, scale, -43.280851226668903f); // (±100*acc-30)*log2(e)
    t = fmaxf(t, -125.0f);
    const float r = t + 12582912.0f;             // round-to-nearest int
    const float n = r - 12582912.0f;
    const float f = t - n;
    float pl = 0.0013333558146428443f;
    pl = fmaf(pl, f, 0.009618129107628477f);
    pl = fmaf(pl, f, 0.05550410866482158f);
    pl = fmaf(pl, f, 0.2402265069591007f);
    pl = fmaf(pl, f, 0.6931471805599453f);
    pl = fmaf(pl, f, 1.0f);
    const uint32_t sb = ((__float_as_uint(r) + (127u - 0x4B400000u)) << 23);
    return pl * __uint_as_float(sb);
}
#define L2E_P 144.26950408889634f
#define L2E_N (-144.26950408889634f)

// 128x128 tile, BK=32, 8 warps (4x2), warp tile 32x64 via m16n8k16 bf16 HMMA.
// Smem XOR swizzle: 16B chunk c at row r lives at chunk (c ^ ((r>>1)&3)).
__global__ void __launch_bounds__(256) gemm_lse_mma() {
    __shared__ __align__(128) __nv_bfloat16 smA[2][BM * BK];
    __shared__ __align__(128) __nv_bfloat16 smB[2][BN * BK];
    __shared__ float rowAcc[BM];
    __shared__ float colAcc[BN];

    const int tid  = threadIdx.x;
    const int lane = tid & 31;
    const int wid  = tid >> 5;
    const int wm   = wid >> 1;        // 0..3
    const int wn   = wid & 1;         // 0..1
    const int bx = blockIdx.x, by = blockIdx.y;

    if (tid < BM) { rowAcc[tid] = 0.f; colAcc[tid] = 0.f; }

    const uint32_t aBase = smem_u32(&smA[0][0]);
    const uint32_t bBase = smem_u32(&smB[0][0]);

    // cp.async assignments: 512 16B-chunks per tile, 2 per thread per tile
    uint32_t dstA[2], dstB[2];
    const __nv_bfloat16* srcA[2];
    const __nv_bfloat16* srcB[2];
    #pragma unroll
    for (int it = 0; it < 2; ++it) {
        const int c = tid + it * 256, row = c >> 2, cc = c & 3;
        const int sw = cc ^ ((row >> 1) & 3);
        dstA[it] = aBase + row * 64 + sw * 16;
        dstB[it] = bBase + row * 64 + sw * 16;
        srcA[it] = g_tdh + (size_t)(by * BM + row) * D + cc * 8;
        srcB[it] = g_imh + (size_t)(bx * BN + row) * D + cc * 8;
    }

    // ldmatrix addresses (stage-0; add s*8192 for stage 1)
    uint32_t aLd[2][2], bLd[2][4];   // [ks][mt], [ks][pair]
    {
        const int rA  = wm * 32 + (lane & 7) + (lane & 8);
        const int cAk = (lane >> 4);
        const int rB  = wn * 64 + (lane & 7) + ((lane & 16) >> 1);
        const int cBk = (lane >> 3) & 1;
        #pragma unroll
        for (int ks = 0; ks < 2; ++ks) {
            #pragma unroll
            for (int mt = 0; mt < 2; ++mt) {
                const int row = rA + mt * 16, ch = ks * 2 + cAk;
                aLd[ks][mt] = aBase + row * 64 + ((ch ^ ((row >> 1) & 3)) * 16);
            }
            #pragma unroll
            for (int pr = 0; pr < 4; ++pr) {
                const int row = rB + pr * 16, ch = ks * 2 + cBk;
                bLd[ks][pr] = bBase + row * 64 + ((ch ^ ((row >> 1) & 3)) * 16);
            }
        }
    }

    float acc[2][8][4];
    #pragma unroll
    for (int mt = 0; mt < 2; ++mt)
        #pragma unroll
        for (int nt = 0; nt < 8; ++nt)
            #pragma unroll
            for (int k = 0; k < 4; ++k) acc[mt][nt][k] = 0.f;

    // prologue
    #pragma unroll
    for (int kb0 = 0; kb0 < 2; ++kb0) {
        #pragma unroll
        for (int it = 0; it < 2; ++it) {
            asm volatile("cp.async.cg.shared.global [%0], [%1], 16;"
                :: "r"(dstA[it] + kb0 * 8192u), "l"(srcA[it] + kb0 * BK));
            asm volatile("cp.async.cg.shared.global [%0], [%1], 16;"
                :: "r"(dstB[it] + kb0 * 8192u), "l"(srcB[it] + kb0 * BK));
        }
        asm volatile("cp.async.commit_group;" ::: "memory");
    }

    #pragma unroll
    for (int kb = 0; kb < NKB; ++kb) {
        const int s = kb & 1;
        const uint32_t so = (uint32_t)s * 8192u;
        if (kb < NKB - 2) asm volatile("cp.async.wait_group 1;" ::: "memory");
        else              asm volatile("cp.async.wait_group 0;" ::: "memory");
        __syncthreads();

        uint32_t af[2][2][4], bf[2][4][4];
        #pragma unroll
        for (int ks = 0; ks < 2; ++ks) {
            #pragma unroll
            for (int mt = 0; mt < 2; ++mt)
                LDSM_X4(af[ks][mt][0], af[ks][mt][1], af[ks][mt][2], af[ks][mt][3],
                        aLd[ks][mt] + so);
            #pragma unroll
            for (int pr = 0; pr < 4; ++pr)
                LDSM_X4(bf[ks][pr][0], bf[ks][pr][1], bf[ks][pr][2], bf[ks][pr][3],
                        bLd[ks][pr] + so);
        }
        __syncthreads();                    // all reads of stage s done

        if (kb + 2 < NKB) {                 // refill stage s for kb+2
            #pragma unroll
            for (int it = 0; it < 2; ++it) {
                asm volatile("cp.async.cg.shared.global [%0], [%1], 16;"
                    :: "r"(dstA[it] + so), "l"(srcA[it] + (kb + 2) * BK));
                asm volatile("cp.async.cg.shared.global [%0], [%1], 16;"
                    :: "r"(dstB[it] + so), "l"(srcB[it] + (kb + 2) * BK));
            }
            asm volatile("cp.async.commit_group;" ::: "memory");
        }

        #pragma unroll
        for (int ks = 0; ks < 2; ++ks)
            #pragma unroll
            for (int mt = 0; mt < 2; ++mt)
                #pragma unroll
                for (int nt = 0; nt < 8; ++nt) {
                    const uint32_t b0 = bf[ks][nt >> 1][(nt & 1) * 2 + 0];
                    const uint32_t b1 = bf[ks][nt >> 1][(nt & 1) * 2 + 1];
                    MMA16816(acc[mt][nt], af[ks][mt], b0, b1);
                }
    }

    // ---- fused epilogue: v = exp(x-30) + exp(-x-30); row/col reduce ----
    // C frag: c0,c1 = row lane/4, cols 2*(lane&3), +1 ; c2,c3 = row+8
    float rp[2][2];
    float cp[8][2];
    #pragma unroll
    for (int mt = 0; mt < 2; ++mt) { rp[mt][0] = 0.f; rp[mt][1] = 0.f; }
    #pragma unroll
    for (int nt = 0; nt < 8; ++nt) { cp[nt][0] = 0.f; cp[nt][1] = 0.f; }

    const int row0g = by * BM + wm * 32 + (lane >> 2);
    const int col0g = bx * BN + wn * 64 + (lane & 3) * 2;

    #pragma unroll
    for (int mt = 0; mt < 2; ++mt) {
        const int r0 = row0g + mt * 16;
        const bool ok0 = r0 < P2, ok1 = (r0 + 8) < P2;
        #pragma unroll
        for (int nt = 0; nt < 8; ++nt) {
            const int c0 = col0g + nt * 8;
            const bool okc0 = c0 < P2, okc1 = (c0 + 1) < P2;
            float e0 = fast_exp_shift(acc[mt][nt][0], L2E_P)
                     + fast_exp_shift(acc[mt][nt][0], L2E_N);
            float e1 = fast_exp_shift(acc[mt][nt][1], L2E_P)
                     + fast_exp_shift(acc[mt][nt][1], L2E_N);
            float e2 = fast_exp_shift(acc[mt][nt][2], L2E_P)
                     + fast_exp_shift(acc[mt][nt][2], L2E_N);
            float e3 = fast_exp_shift(acc[mt][nt][3], L2E_P)
                     + fast_exp_shift(acc[mt][nt][3], L2E_N);
            e0 = (ok0 && okc0) ? e0 : 0.f;
            e1 = (ok0 && okc1) ? e1 : 0.f;
            e2 = (ok1 && okc0) ? e2 : 0.f;
            e3 = (ok1 && okc1) ? e3 : 0.f;
            rp[mt][0] += e0 + e1;
            rp[mt][1] += e2 + e3;
            cp[nt][0] += e0 + e2;
            cp[nt][1] += e1 + e3;
        }
    }

    // row partials: reduce over the 4 lanes sharing a row (lane&3 varies)
    #pragma unroll
    for (int mt = 0; mt < 2; ++mt) {
        #pragma unroll
        for (int h = 0; h < 2; ++h) {
            float v = rp[mt][h];
            v += __shfl_xor_sync(0xffffffffu, v, 1);
            v += __shfl_xor_sync(0xffffffffu, v, 2);
            if ((lane & 3) == 0)
                atomicAdd(&rowAcc[wm * 32 + mt * 16 + (lane >> 2) + h * 8], v);
        }
    }
    // col partials: reduce over the 8 lanes sharing a col (lane>>2 varies)
    #pragma unroll
    for (int nt = 0; nt < 8; ++nt) {
        #pragma unroll
        for (int h = 0; h < 2; ++h) {
            float v = cp[nt][h];
            v += __shfl_xor_sync(0xffffffffu, v, 4);
            v += __shfl_xor_sync(0xffffffffu, v, 8);
            v += __shfl_xor_sync(0xffffffffu, v, 16);
            if (lane < 4)
                atomicAdd(&colAcc[wn * 64 + nt * 8 + lane * 2 + h], v);
        }
    }

    __syncthreads();
    if (tid < BM) {
        const int gr = by * BM + tid;
        const int gc = bx * BN + tid;
        if (gr < P2) atomicAdd(&g_rowSum[gr], rowAcc[tid]);
        if (gc < P2) atomicAdd(&g_colSum[gc], colAcc[tid]);
    }
}

__global__ __launch_bounds__(256) void finalize_kernel(float* __restrict__ out) {
    __shared__ float red[8];
    const int t = threadIdx.x;
    const int p0 = blockIdx.x * 256 + t;
    float s = 0.f;
    if (p0 < P2)
        s = SHIFT + 0.5f * (logf(g_rowSum[p0]) + logf(g_colSum[p0])) - g_diag[p0];
    const float tot = block_reduce_sum_256(s, red);
    if (t == 0) atomicAdd(out, tot / (float)P2);
}

extern "C" void kernel_launch(void* const* d_in, const int* in_sizes, int n_in,
                              void* d_out, int out_size) {
    const float* txtf = (const float*)d_in[0];
    const float* imgf = (const float*)d_in[1];
    (void)in_sizes; (void)n_in; (void)out_size;
    float* out = (float*)d_out;

    zero_sums_kernel<<<(P2PAD + 255) / 256, 256>>>(out);
    pairdiff_kernel<<<P2PAD, 256>>>(txtf, imgf);
    gemm_lse_mma<<<dim3(P2PAD / BN, P2PAD / BM), 256>>>();
    finalize_kernel<<<(P2 + 255) / 256, 256>>>(out);
}

// round 6
// speedup vs baseline: 25.1401x; 1.3532x over previous
#include <cuda_runtime.h>
#include <cstdint>

// DeltaLoss via rank-96 factorization: td/im pair-diffs live in the span of the
// 96 input rows, so mma[p,q] = 100*st_p*si_q*(G[ip,iq]-G[ip,jq]-G[jp,iq]+G[jp,jq])
// with G = txtf@imgf^T (96x96). Precompute W[r][q] = si_q*(G[r,iq]-G[r,jq]);
// then each logit is one smem diff + FMA + two ex2. No GEMM over D at all.
// Half pair set S (i<j): antisymmetry gives rowSum_full[p] = sum_q e^{x-30}+e^{-x-30}.
// SHIFT=30: x<=100 -> no overflow; sums >= e^{diag-30} stay normal fp32.

#define NN    96
#define D     512
#define P2    4560            // NN*(NN-1)/2
#define P2PAD 4608            // 18 * 256
#define PBLK  256
#define QBLK  128
#define K2C   (-43.28085122666891f)   // -30*log2(e)
#define L2E100 144.26950408889634f    // 100*log2(e)

// ---- scratch ----
__device__ float g_gtt[NN * NN];
__device__ float g_gii[NN * NN];
__device__ float g_gti[NN * NN];
__device__ uint32_t g_ij[P2PAD];      // i | j<<8
__device__ float g_k1[P2PAD];         // 100*log2e*st_p  (0 for pad)
__device__ float g_si[P2PAD];         // 1/(||im||+eps)   (0 for pad)
__device__ float g_diag[P2PAD];
__device__ float g_W[(size_t)NN * P2PAD];
__device__ float g_rowSum[P2PAD];
__device__ float g_colSum[P2PAD];

__device__ __forceinline__ float ex2f(float x) {
    float y;
    asm("ex2.approx.f32 %0, %1;" : "=f"(y) : "f"(x));
    return y;
}

__device__ __forceinline__ float block_reduce_sum_256(float v, float* red) {
    #pragma unroll
    for (int o = 16; o > 0; o >>= 1) v += __shfl_xor_sync(0xffffffffu, v, o);
    const int t = threadIdx.x;
    __syncthreads();
    if ((t & 31) == 0) red[t >> 5] = v;
    __syncthreads();
    float r = 0.f;
    #pragma unroll
    for (int w = 0; w < 8; ++w) r += red[w];
    return r;
}

// ---- Gram matrices: one block per left row b; 8 warps cover 3*96 dots ----
__global__ __launch_bounds__(256) void gram_kernel(const float* __restrict__ txtf,
                                                   const float* __restrict__ imgf) {
    __shared__ float stb[D], sub[D];
    const int b = blockIdx.x, t = threadIdx.x;
    stb[t] = txtf[b * D + t];  stb[t + 256] = txtf[b * D + t + 256];
    sub[t] = imgf[b * D + t];  sub[t + 256] = imgf[b * D + t + 256];
    __syncthreads();
    const int w = t >> 5, lane = t & 31;
    for (int d = w; d < 3 * NN; d += 8) {
        const int which = d / NN, r = d - which * NN;
        const float* __restrict__ vec = (which == 0) ? (txtf + r * D) : (imgf + r * D);
        const float* __restrict__ sm  = (which == 1) ? sub : stb;
        float s = 0.f;
        #pragma unroll
        for (int e = 0; e < D / 32; ++e) s = fmaf(sm[lane + e * 32], vec[lane + e * 32], s);
        #pragma unroll
        for (int o = 16; o > 0; o >>= 1) s += __shfl_xor_sync(0xffffffffu, s, o);
        if (lane == 0) {
            float* dst = (which == 0) ? g_gtt : ((which == 1) ? g_gii : g_gti);
            dst[b * NN + r] = s;
        }
    }
}

// ---- per-pair metadata (+ zero accumulators) ----
__global__ __launch_bounds__(256) void meta_kernel(float* __restrict__ out) {
    const int p = blockIdx.x * 256 + threadIdx.x;   // grid exactly covers P2PAD
    g_rowSum[p] = 0.f;
    g_colSum[p] = 0.f;
    if (p == 0) out[0] = 0.f;
    if (p >= P2) { g_ij[p] = 0u; g_k1[p] = 0.f; g_si[p] = 0.f; g_diag[p] = 0.f; return; }

    // triangular index -> (i, j), i<j, lexicographic. off(i) = i*(191-i)/2 for NN=96.
    const float disc = (2.f * NN - 1.f) * (2.f * NN - 1.f) - 8.f * (float)p;
    int i = (int)(((2.f * NN - 1.f) - sqrtf(disc)) * 0.5f);
    i = i < 0 ? 0 : (i > NN - 2 ? NN - 2 : i);
    while (i > 0 && p < i * (191 - i) / 2) --i;
    while (p >= (i + 1) * (190 - i) / 2) ++i;
    const int j = i + 1 + (p - i * (191 - i) / 2);

    const float ntt = g_gtt[i * NN + i] - 2.f * g_gtt[i * NN + j] + g_gtt[j * NN + j];
    const float nii = g_gii[i * NN + i] - 2.f * g_gii[i * NN + j] + g_gii[j * NN + j];
    const float st = 1.f / (sqrtf(ntt) + 1e-8f);
    const float si = 1.f / (sqrtf(nii) + 1e-8f);
    g_ij[p] = (uint32_t)i | ((uint32_t)j << 8);
    g_k1[p] = L2E100 * st;
    g_si[p] = si;
    g_diag[p] = 100.f * st * si *
        (g_gti[i * NN + i] - g_gti[i * NN + j] - g_gti[j * NN + i] + g_gti[j * NN + j]);
}

// ---- W[r][q] = si_q * (Gti[r][i_q] - Gti[r][j_q]) ----
__global__ __launch_bounds__(256) void w_kernel() {
    const int q = blockIdx.x * 256 + threadIdx.x;
    const int r = blockIdx.y;
    const uint32_t ij = g_ij[q];
    const float si = g_si[q];
    const float w = si * (g_gti[r * NN + (ij & 255u)] - g_gti[r * NN + (ij >> 8)]);
    g_W[(size_t)r * P2PAD + q] = w;   // pad q: si=0 -> 0
}

// ---- main: 256p x 128q per block; e = 2^t + 2^(2*K2-t), t = k1*(wi-wj)+K2 ----
__global__ void __launch_bounds__(256) lse_main() {
    extern __shared__ float sm[];
    float* Wsm = sm;                                   // [96][QBLK]
    float* k1sm = sm + NN * QBLK;                      // [PBLK]
    uint32_t* ijsm = (uint32_t*)(k1sm + PBLK);         // [PBLK]
    float* rowAcc = (float*)(ijsm + PBLK);             // [PBLK]
    float* colAcc = rowAcc + PBLK;                     // [QBLK]

    const int tid = threadIdx.x;
    const int q0 = blockIdx.x * QBLK;
    const int p0 = blockIdx.y * PBLK;

    // stage W tile (96 x 128 floats) via float4: 3072 float4 / 256 thr = 12 each
    #pragma unroll
    for (int k = 0; k < 12; ++k) {
        const int f4 = tid + k * 256;
        const int r = f4 >> 5, c = f4 & 31;
        ((float4*)Wsm)[f4] = *(const float4*)(g_W + (size_t)r * P2PAD + q0 + c * 4);
    }
    k1sm[tid] = g_k1[p0 + tid];
    ijsm[tid] = g_ij[p0 + tid];
    rowAcc[tid] = 0.f;
    if (tid < QBLK) colAcc[tid] = 0.f;
    __syncthreads();

    const int w = tid >> 5, lane = tid & 31;
    const int qoff = (w & 3) * 32;          // 4 q-chunks of 32
    const int ph = (w >> 2) * 128;          // 2 p-halves of 128
    float col = 0.f;

    #pragma unroll 4
    for (int pp = 0; pp < 128; ++pp) {
        const int p = ph + pp;
        const uint32_t ij = ijsm[p];
        const float k1 = k1sm[p];
        const float wi = Wsm[(ij & 255u) * QBLK + qoff + lane];
        const float wj = Wsm[(ij >> 8) * QBLK + qoff + lane];
        const float t = fmaf(wi - wj, k1, K2C);
        const float e = ex2f(t) + ex2f(2.f * K2C - t);
        col += e;
        float r = e;
        r += __shfl_xor_sync(0xffffffffu, r, 16);
        r += __shfl_xor_sync(0xffffffffu, r, 8);
        r += __shfl_xor_sync(0xffffffffu, r, 4);
        r += __shfl_xor_sync(0xffffffffu, r, 2);
        r += __shfl_xor_sync(0xffffffffu, r, 1);
        if (lane == 0) atomicAdd(&rowAcc[p], r);
    }
    atomicAdd(&colAcc[qoff + lane], col);
    __syncthreads();

    atomicAdd(&g_rowSum[p0 + tid], rowAcc[tid]);
    if (tid < QBLK) atomicAdd(&g_colSum[q0 + tid], colAcc[tid]);
}

__global__ __launch_bounds__(256) void finalize_kernel(float* __restrict__ out) {
    __shared__ float red[8];
    const int t = threadIdx.x;
    const int p = blockIdx.x * 256 + t;
    float s = 0.f;
    if (p < P2)
        s = 30.0f + 0.5f * (logf(g_rowSum[p]) + logf(g_colSum[p])) - g_diag[p];
    const float tot = block_reduce_sum_256(s, red);
    if (t == 0) atomicAdd(out, tot / (float)P2);
}

extern "C" void kernel_launch(void* const* d_in, const int* in_sizes, int n_in,
                              void* d_out, int out_size) {
    const float* txtf = (const float*)d_in[0];
    const float* imgf = (const float*)d_in[1];
    (void)in_sizes; (void)n_in; (void)out_size;
    float* out = (float*)d_out;

    const int smem = (NN * QBLK + PBLK * 3 + QBLK) * 4;   // 53760 B
    static int configured = 0;
    if (!configured) {
        cudaFuncSetAttribute(lse_main, cudaFuncAttributeMaxDynamicSharedMemorySize, smem);
        configured = 1;
    }

    gram_kernel<<<NN, 256>>>(txtf, imgf);
    meta_kernel<<<P2PAD / 256, 256>>>(out);
    w_kernel<<<dim3(P2PAD / 256, NN), 256>>>();
    lse_main<<<dim3(P2PAD / QBLK, P2PAD / PBLK), 256, smem>>>();
    finalize_kernel<<<P2PAD / 256, 256>>>(out);
}

// round 7
// speedup vs baseline: 40.6755x; 1.6180x over previous
#include <cuda_runtime.h>
#include <cstdint>

// DeltaLoss via rank-96 factorization (see R6). This round restructures lse_main:
// warp iterates p (uniform), lanes own 4 consecutive q via float4 LDS; row sums
// reduce once per 128 entries, col sums live in registers. Pad entries are
// killed by driving the exp2 base to -2000 (both terms underflow to 0).

#define NN    96
#define D     512
#define P2    4560            // NN*(NN-1)/2
#define P2PAD 4608            // 18 * 256
#define PBLK  256
#define QBLK  128
#define K2C   (-43.28085122666891f)   // -30*log2(e)
#define L2E100 144.26950408889634f    // 100*log2(e)

// ---- scratch ----
__device__ float g_gtt[NN * NN];
__device__ float g_gii[NN * NN];
__device__ float g_gti[NN * NN];
__device__ uint32_t g_ij[P2PAD];      // i | j<<8
__device__ float g_k1[P2PAD];         // 100*log2e*st_p  (0 for pad)
__device__ float g_si[P2PAD];         // 1/(||im||+eps)   (0 for pad)
__device__ float g_diag[P2PAD];
__device__ float g_W[(size_t)NN * P2PAD];
__device__ float g_rowSum[P2PAD];
__device__ float g_colSum[P2PAD];

__device__ __forceinline__ float ex2f(float x) {
    float y;
    asm("ex2.approx.f32 %0, %1;" : "=f"(y) : "f"(x));
    return y;
}

__device__ __forceinline__ float block_reduce_sum_256(float v, float* red) {
    #pragma unroll
    for (int o = 16; o > 0; o >>= 1) v += __shfl_xor_sync(0xffffffffu, v, o);
    const int t = threadIdx.x;
    __syncthreads();
    if ((t & 31) == 0) red[t >> 5] = v;
    __syncthreads();
    float r = 0.f;
    #pragma unroll
    for (int w = 0; w < 8; ++w) r += red[w];
    return r;
}

// ---- Gram matrices: one block per left row b; float4 loads ----
__global__ __launch_bounds__(256) void gram_kernel(const float* __restrict__ txtf,
                                                   const float* __restrict__ imgf) {
    __shared__ float stb[D], sub[D];
    const int b = blockIdx.x, t = threadIdx.x;
    ((float4*)stb)[t % 128] = ((const float4*)(txtf + b * D))[t % 128];
    ((float4*)sub)[t % 128] = ((const float4*)(imgf + b * D))[t % 128];
    __syncthreads();
    const int w = t >> 5, lane = t & 31;
    for (int d = w; d < 3 * NN; d += 8) {
        const int which = d / NN, r = d - which * NN;
        const float4* __restrict__ vec = (const float4*)((which == 0) ? (txtf + r * D)
                                                                       : (imgf + r * D));
        const float4* __restrict__ smv = (const float4*)((which == 1) ? sub : stb);
        float s = 0.f;
        #pragma unroll
        for (int e = 0; e < 4; ++e) {
            const float4 a = smv[lane + e * 32];
            const float4 g = vec[lane + e * 32];
            s = fmaf(a.x, g.x, s); s = fmaf(a.y, g.y, s);
            s = fmaf(a.z, g.z, s); s = fmaf(a.w, g.w, s);
        }
        #pragma unroll
        for (int o = 16; o > 0; o >>= 1) s += __shfl_xor_sync(0xffffffffu, s, o);
        if (lane == 0) {
            float* dst = (which == 0) ? g_gtt : ((which == 1) ? g_gii : g_gti);
            dst[b * NN + r] = s;
        }
    }
}

// ---- per-pair metadata (+ zero accumulators) ----
__global__ __launch_bounds__(256) void meta_kernel(float* __restrict__ out) {
    const int p = blockIdx.x * 256 + threadIdx.x;   // grid exactly covers P2PAD
    g_rowSum[p] = 0.f;
    g_colSum[p] = 0.f;
    if (p == 0) out[0] = 0.f;
    if (p >= P2) { g_ij[p] = 0u; g_k1[p] = 0.f; g_si[p] = 0.f; g_diag[p] = 0.f; return; }

    // triangular index -> (i, j), i<j, lexicographic. off(i) = i*(191-i)/2 for NN=96.
    const float disc = (2.f * NN - 1.f) * (2.f * NN - 1.f) - 8.f * (float)p;
    int i = (int)(((2.f * NN - 1.f) - sqrtf(disc)) * 0.5f);
    i = i < 0 ? 0 : (i > NN - 2 ? NN - 2 : i);
    while (i > 0 && p < i * (191 - i) / 2) --i;
    while (p >= (i + 1) * (190 - i) / 2) ++i;
    const int j = i + 1 + (p - i * (191 - i) / 2);

    const float ntt = g_gtt[i * NN + i] - 2.f * g_gtt[i * NN + j] + g_gtt[j * NN + j];
    const float nii = g_gii[i * NN + i] - 2.f * g_gii[i * NN + j] + g_gii[j * NN + j];
    const float st = 1.f / (sqrtf(ntt) + 1e-8f);
    const float si = 1.f / (sqrtf(nii) + 1e-8f);
    g_ij[p] = (uint32_t)i | ((uint32_t)j << 8);
    g_k1[p] = L2E100 * st;
    g_si[p] = si;
    g_diag[p] = 100.f * st * si *
        (g_gti[i * NN + i] - g_gti[i * NN + j] - g_gti[j * NN + i] + g_gti[j * NN + j]);
}

// ---- W[r][q] = si_q * (Gti[r][i_q] - Gti[r][j_q]) ----
__global__ __launch_bounds__(256) void w_kernel() {
    const int q = blockIdx.x * 256 + threadIdx.x;
    const int r = blockIdx.y;
    const uint32_t ij = g_ij[q];
    const float si = g_si[q];
    const float w = si * (g_gti[r * NN + (ij & 255u)] - g_gti[r * NN + (ij >> 8)]);
    g_W[(size_t)r * P2PAD + q] = w;   // pad q: si=0 -> 0
}

// ---- main: block = 256p x 128q. Warp w owns p in [w*32, w*32+32), lanes own
//      q = 4*lane..4*lane+3 (float4). e = 2^t + 2^tn; pad p -> base=-2000 -> e=0.
__global__ void __launch_bounds__(256) lse_main() {
    extern __shared__ float sm[];
    float* Wsm = sm;                                   // [96][QBLK]
    float* k1sm = sm + NN * QBLK;                      // [PBLK]
    uint32_t* ijsm = (uint32_t*)(k1sm + PBLK);         // [PBLK]

    const int tid = threadIdx.x;
    const int q0 = blockIdx.x * QBLK;
    const int p0 = blockIdx.y * PBLK;

    // stage W tile (96 x 128 floats) via float4: 3072 float4 / 256 thr = 12 each
    #pragma unroll
    for (int k = 0; k < 12; ++k) {
        const int f4 = tid + k * 256;
        const int r = f4 >> 5, c = f4 & 31;
        ((float4*)Wsm)[f4] = *(const float4*)(g_W + (size_t)r * P2PAD + q0 + c * 4);
    }
    k1sm[tid] = g_k1[p0 + tid];
    ijsm[tid] = g_ij[p0 + tid];
    __syncthreads();

    const int w = tid >> 5, lane = tid & 31;
    const int qq = 4 * lane;
    const int gq = q0 + qq;
    // q-pad mask (kills pad-q leakage into rowSum)
    const float mq0 = (gq + 0 < P2) ? 1.f : 0.f;
    const float mq1 = (gq + 1 < P2) ? 1.f : 0.f;
    const float mq2 = (gq + 2 < P2) ? 1.f : 0.f;
    const float mq3 = (gq + 3 < P2) ? 1.f : 0.f;

    float c0 = 0.f, c1 = 0.f, c2 = 0.f, c3 = 0.f;
    const int pbase = w * 32;

    #pragma unroll 4
    for (int pp = 0; pp < 32; ++pp) {
        const int p = pbase + pp;
        const uint32_t ij = ijsm[p];                   // warp-uniform broadcast
        const float k1 = k1sm[p];
        const float base = (p0 + p < P2) ? K2C : -2000.f;  // pad p -> both ex2 underflow
        const float4 wi = *(const float4*)&Wsm[(ij & 255u) * QBLK + qq];
        const float4 wj = *(const float4*)&Wsm[(ij >> 8) * QBLK + qq];

        const float d0 = wi.x - wj.x, d1 = wi.y - wj.y;
        const float d2 = wi.z - wj.z, d3 = wi.w - wj.w;
        const float e0 = ex2f(fmaf(d0, k1, base)) + ex2f(fmaf(d0, -k1, base));
        const float e1 = ex2f(fmaf(d1, k1, base)) + ex2f(fmaf(d1, -k1, base));
        const float e2 = ex2f(fmaf(d2, k1, base)) + ex2f(fmaf(d2, -k1, base));
        const float e3 = ex2f(fmaf(d3, k1, base)) + ex2f(fmaf(d3, -k1, base));

        c0 += e0; c1 += e1; c2 += e2; c3 += e3;        // register col accumulators

        float rs = fmaf(e0, mq0, 0.f);
        rs = fmaf(e1, mq1, rs);
        rs = fmaf(e2, mq2, rs);
        rs = fmaf(e3, mq3, rs);
        rs += __shfl_xor_sync(0xffffffffu, rs, 16);
        rs += __shfl_xor_sync(0xffffffffu, rs, 8);
        rs += __shfl_xor_sync(0xffffffffu, rs, 4);
        rs += __shfl_xor_sync(0xffffffffu, rs, 2);
        rs += __shfl_xor_sync(0xffffffffu, rs, 1);
        if (lane == 0) atomicAdd(&g_rowSum[p0 + p], rs);
    }

    // col sums: pad-p contributions already zero (base trick); pad-q lands in pad slots
    atomicAdd(&g_colSum[gq + 0], c0);
    atomicAdd(&g_colSum[gq + 1], c1);
    atomicAdd(&g_colSum[gq + 2], c2);
    atomicAdd(&g_colSum[gq + 3], c3);
}

__global__ __launch_bounds__(256) void finalize_kernel(float* __restrict__ out) {
    __shared__ float red[8];
    const int t = threadIdx.x;
    const int p = blockIdx.x * 256 + t;
    float s = 0.f;
    if (p < P2)
        s = 30.0f + 0.5f * (logf(g_rowSum[p]) + logf(g_colSum[p])) - g_diag[p];
    const float tot = block_reduce_sum_256(s, red);
    if (t == 0) atomicAdd(out, tot / (float)P2);
}

extern "C" void kernel_launch(void* const* d_in, const int* in_sizes, int n_in,
                              void* d_out, int out_size) {
    const float* txtf = (const float*)d_in[0];
    const float* imgf = (const float*)d_in[1];
    (void)in_sizes; (void)n_in; (void)out_size;
    float* out = (float*)d_out;

    const int smem = (NN * QBLK + PBLK * 2) * 4;   // 51200 B
    static int configured = 0;
    if (!configured) {
        cudaFuncSetAttribute(lse_main, cudaFuncAttributeMaxDynamicSharedMemorySize, smem);
        configured = 1;
    }

    gram_kernel<<<NN, 256>>>(txtf, imgf);
    meta_kernel<<<P2PAD / 256, 256>>>(out);
    w_kernel<<<dim3(P2PAD / 256, NN), 256>>>();
    lse_main<<<dim3(P2PAD / QBLK, P2PAD / PBLK), 256, smem>>>();
    finalize_kernel<<<P2PAD / 256, 256>>>(out);
}

// round 8
// speedup vs baseline: 48.8046x; 1.1999x over previous
#include <cuda_runtime.h>
#include <cstdint>

// DeltaLoss, rank-96 factorization (see R6/R7). R8: 3 launches total.
//   gram  : G_tt, G_ii, G_ti (96x96 each), grid (96,3)
//   meta  : per-pair (i,j), k1=100*log2e/||td||, si=1/||im||, diag; zero sums
//   lse   : per block builds W tile in smem from Gti (no g_W), fused LSE loop,
//           last block (ticket) computes the final loss (no finalize kernel).
// SHIFT=30 fixed-shift LSE: x<=100 -> no overflow; sums stay normal fp32.

#define NN    96
#define D     512
#define P2    4560            // NN*(NN-1)/2
#define P2PAD 4608            // 36*128 = 18*256
#define PBLK  256
#define QBLK  128
#define GQ    (P2PAD / QBLK)  // 36
#define GP    (P2PAD / PBLK)  // 18
#define NBLOCKS (GQ * GP)     // 648
#define K2C   (-43.28085122666891f)   // -30*log2(e)
#define L2E100 144.26950408889634f    // 100*log2(e)

// ---- scratch ----
__device__ float g_gtt[NN * NN];
__device__ float g_gii[NN * NN];
__device__ float g_gti[NN * NN];
__device__ uint32_t g_ij[P2PAD];      // i | j<<8
__device__ float g_k1[P2PAD];         // 100*log2e*st_p  (0 for pad)
__device__ float g_si[P2PAD];         // 1/(||im||+eps)   (0 for pad)
__device__ float g_diag[P2PAD];
__device__ float g_rowSum[P2PAD];
__device__ float g_colSum[P2PAD];
__device__ unsigned int g_done;

__device__ __forceinline__ float ex2f(float x) {
    float y;
    asm("ex2.approx.f32 %0, %1;" : "=f"(y) : "f"(x));
    return y;
}
__device__ __forceinline__ uint32_t smem_u32(const void* p) {
    uint32_t a;
    asm("{ .reg .u64 t; cvta.to.shared.u64 t, %1; cvt.u32.u64 %0, t; }" : "=r"(a) : "l"(p));
    return a;
}

__device__ __forceinline__ float block_reduce_sum_256(float v, float* red) {
    #pragma unroll
    for (int o = 16; o > 0; o >>= 1) v += __shfl_xor_sync(0xffffffffu, v, o);
    const int t = threadIdx.x;
    __syncthreads();
    if ((t & 31) == 0) red[t >> 5] = v;
    __syncthreads();
    float r = 0.f;
    #pragma unroll
    for (int w = 0; w < 8; ++w) r += red[w];
    return r;
}

// ---- Gram: block (b, which) computes one row of one Gram matrix set ----
__global__ __launch_bounds__(256) void gram_kernel(const float* __restrict__ txtf,
                                                   const float* __restrict__ imgf) {
    __shared__ float srow[D];
    const int b = blockIdx.x, which = blockIdx.y, t = threadIdx.x;
    const float* __restrict__ left = (which == 1) ? imgf : txtf;   // tt/ti use txt row
    if (t < 128) ((float4*)srow)[t] = ((const float4*)(left + b * D))[t];
    __syncthreads();
    const int w = t >> 5, lane = t & 31;
    const float* __restrict__ rvecs = (which == 0) ? txtf : imgf;  // tt: txt; ii/ti: img
    float* __restrict__ dst = (which == 0) ? g_gtt : ((which == 1) ? g_gii : g_gti);
    #pragma unroll
    for (int dd = 0; dd < 12; ++dd) {
        const int r = w + dd * 8;
        const float4* __restrict__ vec = (const float4*)(rvecs + r * D);
        float s = 0.f;
        #pragma unroll
        for (int e = 0; e < 4; ++e) {
            const float4 a = ((const float4*)srow)[lane + e * 32];
            const float4 g = vec[lane + e * 32];
            s = fmaf(a.x, g.x, s); s = fmaf(a.y, g.y, s);
            s = fmaf(a.z, g.z, s); s = fmaf(a.w, g.w, s);
        }
        #pragma unroll
        for (int o = 16; o > 0; o >>= 1) s += __shfl_xor_sync(0xffffffffu, s, o);
        if (lane == 0) dst[b * NN + r] = s;
    }
}

// ---- per-pair metadata + zero accumulators + reset ticket ----
__global__ __launch_bounds__(256) void meta_kernel() {
    const int p = blockIdx.x * 256 + threadIdx.x;   // grid covers P2PAD exactly
    g_rowSum[p] = 0.f;
    g_colSum[p] = 0.f;
    if (p == 0) g_done = 0u;
    if (p >= P2) { g_ij[p] = 0u; g_k1[p] = 0.f; g_si[p] = 0.f; g_diag[p] = 0.f; return; }

    const float disc = (2.f * NN - 1.f) * (2.f * NN - 1.f) - 8.f * (float)p;
    int i = (int)(((2.f * NN - 1.f) - sqrtf(disc)) * 0.5f);
    i = i < 0 ? 0 : (i > NN - 2 ? NN - 2 : i);
    while (i > 0 && p < i * (191 - i) / 2) --i;
    while (p >= (i + 1) * (190 - i) / 2) ++i;
    const int j = i + 1 + (p - i * (191 - i) / 2);

    const float ntt = g_gtt[i * NN + i] - 2.f * g_gtt[i * NN + j] + g_gtt[j * NN + j];
    const float nii = g_gii[i * NN + i] - 2.f * g_gii[i * NN + j] + g_gii[j * NN + j];
    const float st = 1.f / (sqrtf(ntt) + 1e-8f);
    const float si = 1.f / (sqrtf(nii) + 1e-8f);
    g_ij[p] = (uint32_t)i | ((uint32_t)j << 8);
    g_k1[p] = L2E100 * st;
    g_si[p] = si;
    g_diag[p] = 100.f * st * si *
        (g_gti[i * NN + i] - g_gti[i * NN + j] - g_gti[j * NN + i] + g_gti[j * NN + j]);
}

// ---- main: builds W tile in smem, runs fused LSE loop, last block finalizes ----
__global__ void __launch_bounds__(256) lse_main(float* __restrict__ out) {
    extern __shared__ float sm[];
    float* Wsm = sm;                                   // [96][QBLK]
    float* k1sm = sm + NN * QBLK;                      // [PBLK]
    float* bsm  = k1sm + PBLK;                         // [PBLK] exp2 base per p
    uint32_t* offsm = (uint32_t*)(bsm + PBLK);         // [PBLK] packed byte offsets
    float* red = (float*)(offsm + PBLK);               // [8] finalize scratch

    const int tid = threadIdx.x;
    const int q0 = blockIdx.x * QBLK;
    const int p0 = blockIdx.y * PBLK;

    // --- build W tile: Wsm[r][q] = si_q * (Gti[r][i_q] - Gti[r][j_q]) ---
    {
        const int q = tid & 127;
        const int half = tid >> 7;                     // r in [half*48, half*48+48)
        const uint32_t ij = g_ij[q0 + q];
        const float si = g_si[q0 + q];
        const int iq = (int)(ij & 255u), jq = (int)(ij >> 8);
        const float* __restrict__ gi = g_gti + half * 48 * NN;
        #pragma unroll 8
        for (int k = 0; k < 48; ++k) {
            const float a = __ldg(gi + k * NN + iq);
            const float b = __ldg(gi + k * NN + jq);
            Wsm[(half * 48 + k) * QBLK + q] = si * (a - b);
        }
        // per-p metadata
        const int p = p0 + tid;
        k1sm[tid] = g_k1[p];
        bsm[tid]  = (p < P2) ? K2C : -2000.f;          // pad p -> both ex2 underflow
        const uint32_t pij = g_ij[p];
        offsm[tid] = ((pij & 255u) * (QBLK * 4)) | (((pij >> 8) * (QBLK * 4)) << 16);
    }
    __syncthreads();

    const int w = tid >> 5, lane = tid & 31;
    const uint32_t wbase = smem_u32(Wsm) + (uint32_t)lane * 16u;
    const int pbase = w * 32;
    float c0 = 0.f, c1 = 0.f, c2 = 0.f, c3 = 0.f;

    if (q0 + QBLK <= P2) {
        // fast path: all q valid, no masks
        #pragma unroll 8
        for (int pp = 0; pp < 32; ++pp) {
            const int p = pbase + pp;
            const uint32_t off = offsm[p];
            const float k1 = k1sm[p];
            const float base = bsm[p];
            const float4 wi = *(const float4*)__builtin_assume_aligned(
                (const void*)(uintptr_t)0, 16);        // placeholder avoided below
            (void)wi;
            float4 vi, vj;
            asm volatile("ld.shared.v4.f32 {%0,%1,%2,%3}, [%4];"
                : "=f"(vi.x), "=f"(vi.y), "=f"(vi.z), "=f"(vi.w)
                : "r"(wbase + (off & 0xFFFFu)));
            asm volatile("ld.shared.v4.f32 {%0,%1,%2,%3}, [%4];"
                : "=f"(vj.x), "=f"(vj.y), "=f"(vj.z), "=f"(vj.w)
                : "r"(wbase + (off >> 16)));
            const float d0 = vi.x - vj.x, d1 = vi.y - vj.y;
            const float d2 = vi.z - vj.z, d3 = vi.w - vj.w;
            const float e0 = ex2f(fmaf(d0, k1, base)) + ex2f(fmaf(d0, -k1, base));
            const float e1 = ex2f(fmaf(d1, k1, base)) + ex2f(fmaf(d1, -k1, base));
            const float e2 = ex2f(fmaf(d2, k1, base)) + ex2f(fmaf(d2, -k1, base));
            const float e3 = ex2f(fmaf(d3, k1, base)) + ex2f(fmaf(d3, -k1, base));
            c0 += e0; c1 += e1; c2 += e2; c3 += e3;
            float rs = (e0 + e1) + (e2 + e3);
            rs += __shfl_xor_sync(0xffffffffu, rs, 16);
            rs += __shfl_xor_sync(0xffffffffu, rs, 8);
            rs += __shfl_xor_sync(0xffffffffu, rs, 4);
            rs += __shfl_xor_sync(0xffffffffu, rs, 2);
            rs += __shfl_xor_sync(0xffffffffu, rs, 1);
            if (lane == 0) atomicAdd(&g_rowSum[p0 + p], rs);
        }
    } else {
        // masked path: last q block only
        const int gq = q0 + 4 * lane;
        const float mq0 = (gq + 0 < P2) ? 1.f : 0.f;
        const float mq1 = (gq + 1 < P2) ? 1.f : 0.f;
        const float mq2 = (gq + 2 < P2) ? 1.f : 0.f;
        const float mq3 = (gq + 3 < P2) ? 1.f : 0.f;
        #pragma unroll 8
        for (int pp = 0; pp < 32; ++pp) {
            const int p = pbase + pp;
            const uint32_t off = offsm[p];
            const float k1 = k1sm[p];
            const float base = bsm[p];
            float4 vi, vj;
            asm volatile("ld.shared.v4.f32 {%0,%1,%2,%3}, [%4];"
                : "=f"(vi.x), "=f"(vi.y), "=f"(vi.z), "=f"(vi.w)
                : "r"(wbase + (off & 0xFFFFu)));
            asm volatile("ld.shared.v4.f32 {%0,%1,%2,%3}, [%4];"
                : "=f"(vj.x), "=f"(vj.y), "=f"(vj.z), "=f"(vj.w)
                : "r"(wbase + (off >> 16)));
            const float d0 = vi.x - vj.x, d1 = vi.y - vj.y;
            const float d2 = vi.z - vj.z, d3 = vi.w - vj.w;
            const float e0 = ex2f(fmaf(d0, k1, base)) + ex2f(fmaf(d0, -k1, base));
            const float e1 = ex2f(fmaf(d1, k1, base)) + ex2f(fmaf(d1, -k1, base));
            const float e2 = ex2f(fmaf(d2, k1, base)) + ex2f(fmaf(d2, -k1, base));
            const float e3 = ex2f(fmaf(d3, k1, base)) + ex2f(fmaf(d3, -k1, base));
            c0 += e0; c1 += e1; c2 += e2; c3 += e3;
            float rs = fmaf(e0, mq0, 0.f);
            rs = fmaf(e1, mq1, rs);
            rs = fmaf(e2, mq2, rs);
            rs = fmaf(e3, mq3, rs);
            rs += __shfl_xor_sync(0xffffffffu, rs, 16);
            rs += __shfl_xor_sync(0xffffffffu, rs, 8);
            rs += __shfl_xor_sync(0xffffffffu, rs, 4);
            rs += __shfl_xor_sync(0xffffffffu, rs, 2);
            rs += __shfl_xor_sync(0xffffffffu, rs, 1);
            if (lane == 0) atomicAdd(&g_rowSum[p0 + p], rs);
        }
    }

    // col sums (pad p contributed 0; pad q lands in ignored slots)
    const int gq = q0 + 4 * lane;
    atomicAdd(&g_colSum[gq + 0], c0);
    atomicAdd(&g_colSum[gq + 1], c1);
    atomicAdd(&g_colSum[gq + 2], c2);
    atomicAdd(&g_colSum[gq + 3], c3);

    // --- last-block finalize (ticket) ---
    __syncthreads();
    __shared__ unsigned int s_last;
    if (tid == 0) {
        __threadfence();
        s_last = (atomicAdd(&g_done, 1u) == (unsigned)(NBLOCKS - 1)) ? 1u : 0u;
    }
    __syncthreads();
    if (s_last) {
        __threadfence();
        float s = 0.f;
        for (int p = tid; p < P2; p += 256)
            s += 30.0f + 0.5f * (logf(g_rowSum[p]) + logf(g_colSum[p])) - g_diag[p];
        const float tot = block_reduce_sum_256(s, red);
        if (tid == 0) out[0] = tot / (float)P2;
    }
}

extern "C" void kernel_launch(void* const* d_in, const int* in_sizes, int n_in,
                              void* d_out, int out_size) {
    const float* txtf = (const float*)d_in[0];
    const float* imgf = (const float*)d_in[1];
    (void)in_sizes; (void)n_in; (void)out_size;
    float* out = (float*)d_out;

    const int smem = (NN * QBLK + PBLK * 3 + 8) * 4;   // ~52.3 KB
    static int configured = 0;
    if (!configured) {
        cudaFuncSetAttribute(lse_main, cudaFuncAttributeMaxDynamicSharedMemorySize, smem);
        configured = 1;
    }

    gram_kernel<<<dim3(NN, 3), 256>>>(txtf, imgf);
    meta_kernel<<<P2PAD / 256, 256>>>();
    lse_main<<<dim3(GQ, GP), 256, smem>>>(out);
}

// round 9
// speedup vs baseline: 56.2423x; 1.1524x over previous
#include <cuda_runtime.h>
#include <cstdint>

// DeltaLoss, rank-96 factorization. R9: 2 launches.
//  prep : blocks 0..191 -> Gti rows (txt_b . img_r); blocks 192..767 -> warp-per-pair
//         meta (ntt/nii/diag as direct dot products of raw rows) + zero accumulators.
//  lse  : per block builds W tile (96 x 128) in smem from Gti; PBLK=512 p-rows per
//         block; fused exp/row/col reduction; last block (ticket) computes the loss.
// SHIFT=30 fixed-shift LSE: x<=100 -> no overflow; sums stay normal fp32.

#define NN    96
#define D     512
#define P2    4560            // NN*(NN-1)/2
#define P2PAD 4608
#define PBLK  512
#define QBLK  128
#define GQ    (P2PAD / QBLK)  // 36
#define GP    (P2PAD / PBLK)  // 9
#define NBLOCKS (GQ * GP)     // 324
#define NGRAMB 192            // 96 rows x 2 halves
#define NMETAB 576            // 4608 / 8 pairs per block
#define K2C   (-43.28085122666891f)   // -30*log2(e)
#define L2E100 144.26950408889634f    // 100*log2(e)

// ---- scratch ----
__device__ float g_gti[NN * NN];      // txt_a . img_b
__device__ uint32_t g_ij[P2PAD];      // i | j<<8
__device__ float g_k1[P2PAD];         // 100*log2e/(||td||+eps)   (0 for pad)
__device__ float g_si[P2PAD];         // 1/(||im||+eps)           (0 for pad)
__device__ float g_diag[P2PAD];
__device__ float g_rowSum[P2PAD];
__device__ float g_colSum[P2PAD];
__device__ unsigned int g_done;

__device__ __forceinline__ float ex2f(float x) {
    float y;
    asm("ex2.approx.f32 %0, %1;" : "=f"(y) : "f"(x));
    return y;
}
__device__ __forceinline__ uint32_t smem_u32(const void* p) {
    uint32_t a;
    asm("{ .reg .u64 t; cvta.to.shared.u64 t, %1; cvt.u32.u64 %0, t; }" : "=r"(a) : "l"(p));
    return a;
}
__device__ __forceinline__ float warp_sum(float v) {
    #pragma unroll
    for (int o = 16; o > 0; o >>= 1) v += __shfl_xor_sync(0xffffffffu, v, o);
    return v;
}

// ---- prep: Gti (192 blocks) + per-pair meta & zeroing (576 blocks) ----
__global__ __launch_bounds__(256) void prep_kernel(const float* __restrict__ txtf,
                                                   const float* __restrict__ imgf) {
    __shared__ float srow[D];
    const int bid = blockIdx.x;
    const int tid = threadIdx.x;
    const int w = tid >> 5, lane = tid & 31;

    if (bid < NGRAMB) {
        // Gti[b][r] for r in [half*48, half*48+48), 6 rows per warp
        const int b = bid >> 1, half = bid & 1;
        if (tid < 128) ((float4*)srow)[tid] = ((const float4*)(txtf + b * D))[tid];
        __syncthreads();
        #pragma unroll
        for (int k = 0; k < 6; ++k) {
            const int r = half * 48 + w * 6 + k;
            const float4* __restrict__ vec = (const float4*)(imgf + r * D);
            float s0 = 0.f, s1 = 0.f;
            #pragma unroll
            for (int e = 0; e < 4; e += 2) {
                const float4 a0 = ((const float4*)srow)[lane + e * 32];
                const float4 g0 = vec[lane + e * 32];
                const float4 a1 = ((const float4*)srow)[lane + (e + 1) * 32];
                const float4 g1 = vec[lane + (e + 1) * 32];
                s0 = fmaf(a0.x, g0.x, s0); s0 = fmaf(a0.y, g0.y, s0);
                s0 = fmaf(a0.z, g0.z, s0); s0 = fmaf(a0.w, g0.w, s0);
                s1 = fmaf(a1.x, g1.x, s1); s1 = fmaf(a1.y, g1.y, s1);
                s1 = fmaf(a1.z, g1.z, s1); s1 = fmaf(a1.w, g1.w, s1);
            }
            const float s = warp_sum(s0 + s1);
            if (lane == 0) g_gti[b * NN + r] = s;
        }
        return;
    }

    // ---- meta blocks: 8 pairs per block (warp-per-pair) + zeroing ----
    const int m = bid - NGRAMB;
    if (tid < 8)              g_rowSum[m * 8 + tid] = 0.f;
    else if (tid < 16)        g_colSum[m * 8 + tid - 8] = 0.f;
    else if (tid == 16 && m == 0) g_done = 0u;

    const int p = m * 8 + w;
    if (p >= P2) {
        if (p < P2PAD && lane == 0) {
            g_ij[p] = 0u; g_k1[p] = 0.f; g_si[p] = 0.f; g_diag[p] = 0.f;
        }
        return;
    }

    // triangular index -> (i, j), i<j, lexicographic. off(i) = i*(191-i)/2.
    const float disc = (2.f * NN - 1.f) * (2.f * NN - 1.f) - 8.f * (float)p;
    int i = (int)(((2.f * NN - 1.f) - sqrtf(disc)) * 0.5f);
    i = i < 0 ? 0 : (i > NN - 2 ? NN - 2 : i);
    while (i > 0 && p < i * (191 - i) / 2) --i;
    while (p >= (i + 1) * (190 - i) / 2) ++i;
    const int j = i + 1 + (p - i * (191 - i) / 2);

    const float4* __restrict__ ti = (const float4*)(txtf + i * D);
    const float4* __restrict__ tj = (const float4*)(txtf + j * D);
    const float4* __restrict__ ui = (const float4*)(imgf + i * D);
    const float4* __restrict__ uj = (const float4*)(imgf + j * D);
    float ntt = 0.f, nii = 0.f, dd = 0.f;
    #pragma unroll
    for (int e = 0; e < 4; ++e) {
        const float4 a = ti[lane + e * 32], b4 = tj[lane + e * 32];
        const float4 c = ui[lane + e * 32], d4 = uj[lane + e * 32];
        const float t0 = a.x - b4.x, t1 = a.y - b4.y, t2 = a.z - b4.z, t3 = a.w - b4.w;
        const float u0 = c.x - d4.x, u1 = c.y - d4.y, u2 = c.z - d4.z, u3 = c.w - d4.w;
        ntt = fmaf(t0, t0, ntt); ntt = fmaf(t1, t1, ntt);
        ntt = fmaf(t2, t2, ntt); ntt = fmaf(t3, t3, ntt);
        nii = fmaf(u0, u0, nii); nii = fmaf(u1, u1, nii);
        nii = fmaf(u2, u2, nii); nii = fmaf(u3, u3, nii);
        dd  = fmaf(t0, u0, dd);  dd  = fmaf(t1, u1, dd);
        dd  = fmaf(t2, u2, dd);  dd  = fmaf(t3, u3, dd);
    }
    ntt = warp_sum(ntt); nii = warp_sum(nii); dd = warp_sum(dd);
    if (lane == 0) {
        const float st = 1.f / (sqrtf(ntt) + 1e-8f);
        const float si = 1.f / (sqrtf(nii) + 1e-8f);
        g_ij[p] = (uint32_t)i | ((uint32_t)j << 8);
        g_k1[p] = L2E100 * st;
        g_si[p] = si;
        g_diag[p] = 100.f * st * si * dd;
    }
}

// ---- main: W tile in smem, 512p x 128q per block, fused LSE, ticket finalize ----
__global__ void __launch_bounds__(256) lse_main(float* __restrict__ out) {
    extern __shared__ float sm[];
    float* Wsm = sm;                                   // [96][QBLK]
    float* k1sm = sm + NN * QBLK;                      // [PBLK]
    float* bsm  = k1sm + PBLK;                         // [PBLK]
    uint32_t* offsm = (uint32_t*)(bsm + PBLK);         // [PBLK]
    float* red = (float*)(offsm + PBLK);               // [8]

    const int tid = threadIdx.x;
    const int q0 = blockIdx.x * QBLK;
    const int p0 = blockIdx.y * PBLK;

    // --- build W tile: Wsm[r][q] = si_q * (Gti[r][i_q] - Gti[r][j_q]) ---
    {
        const int q = tid & 127;
        const int half = tid >> 7;                     // r in [half*48, half*48+48)
        const uint32_t ij = g_ij[q0 + q];
        const float si = g_si[q0 + q];
        const int iq = (int)(ij & 255u), jq = (int)(ij >> 8);
        const float* __restrict__ gi = g_gti + half * 48 * NN;
        #pragma unroll 8
        for (int k = 0; k < 48; ++k) {
            const float a = __ldg(gi + k * NN + iq);
            const float b = __ldg(gi + k * NN + jq);
            Wsm[(half * 48 + k) * QBLK + q] = si * (a - b);
        }
        #pragma unroll
        for (int r = 0; r < 2; ++r) {
            const int pi = tid + r * 256;
            const int p = p0 + pi;
            k1sm[pi] = g_k1[p];
            bsm[pi]  = (p < P2) ? K2C : -2000.f;       // pad p -> both ex2 underflow
            const uint32_t pij = g_ij[p];
            offsm[pi] = ((pij & 255u) * (QBLK * 4)) | (((pij >> 8) * (QBLK * 4)) << 16);
        }
    }
    __syncthreads();

    const int w = tid >> 5, lane = tid & 31;
    const uint32_t wbase = smem_u32(Wsm) + (uint32_t)lane * 16u;
    const int pbase = w * 64;
    float c0 = 0.f, c1 = 0.f, c2 = 0.f, c3 = 0.f;

    const int gq = q0 + 4 * lane;
    const bool fullq = (q0 + QBLK <= P2);
    const float mq0 = (fullq || gq + 0 < P2) ? 1.f : 0.f;
    const float mq1 = (fullq || gq + 1 < P2) ? 1.f : 0.f;
    const float mq2 = (fullq || gq + 2 < P2) ? 1.f : 0.f;
    const float mq3 = (fullq || gq + 3 < P2) ? 1.f : 0.f;

    #pragma unroll 4
    for (int g = 0; g < 16; ++g) {
        float rsv[4];
        #pragma unroll
        for (int u = 0; u < 4; ++u) {
            const int p = pbase + g * 4 + u;
            const uint32_t off = offsm[p];
            const float k1 = k1sm[p];
            const float base = bsm[p];
            float4 vi, vj;
            asm volatile("ld.shared.v4.f32 {%0,%1,%2,%3}, [%4];"
                : "=f"(vi.x), "=f"(vi.y), "=f"(vi.z), "=f"(vi.w)
                : "r"(wbase + (off & 0xFFFFu)));
            asm volatile("ld.shared.v4.f32 {%0,%1,%2,%3}, [%4];"
                : "=f"(vj.x), "=f"(vj.y), "=f"(vj.z), "=f"(vj.w)
                : "r"(wbase + (off >> 16)));
            const float d0 = vi.x - vj.x, d1 = vi.y - vj.y;
            const float d2 = vi.z - vj.z, d3 = vi.w - vj.w;
            const float e0 = ex2f(fmaf(d0, k1, base)) + ex2f(fmaf(d0, -k1, base));
            const float e1 = ex2f(fmaf(d1, k1, base)) + ex2f(fmaf(d1, -k1, base));
            const float e2 = ex2f(fmaf(d2, k1, base)) + ex2f(fmaf(d2, -k1, base));
            const float e3 = ex2f(fmaf(d3, k1, base)) + ex2f(fmaf(d3, -k1, base));
            c0 += e0; c1 += e1; c2 += e2; c3 += e3;
            if (fullq) {
                rsv[u] = (e0 + e1) + (e2 + e3);
            } else {
                float rs = e0 * mq0;
                rs = fmaf(e1, mq1, rs);
                rs = fmaf(e2, mq2, rs);
                rs = fmaf(e3, mq3, rs);
                rsv[u] = rs;
            }
        }
        // merged 4-way butterfly: lane-group (bit4, bit3) ends with row sum of
        // p = pbase + g*4 + idx, idx = bit4 | (bit3 << 1)
        float v0 = rsv[0] + __shfl_xor_sync(0xffffffffu, rsv[0], 16);
        float t1 = rsv[1] + __shfl_xor_sync(0xffffffffu, rsv[1], 16);
        v0 = (lane & 16) ? t1 : v0;
        float v1 = rsv[2] + __shfl_xor_sync(0xffffffffu, rsv[2], 16);
        float t3 = rsv[3] + __shfl_xor_sync(0xffffffffu, rsv[3], 16);
        v1 = (lane & 16) ? t3 : v1;
        float u0 = v0 + __shfl_xor_sync(0xffffffffu, v0, 8);
        float u1 = v1 + __shfl_xor_sync(0xffffffffu, v1, 8);
        u0 = (lane & 8) ? u1 : u0;
        u0 += __shfl_xor_sync(0xffffffffu, u0, 4);
        u0 += __shfl_xor_sync(0xffffffffu, u0, 2);
        u0 += __shfl_xor_sync(0xffffffffu, u0, 1);
        if ((lane & 7) == 0) {
            const int idx = ((lane >> 4) & 1) | ((lane >> 2) & 2);
            atomicAdd(&g_rowSum[p0 + pbase + g * 4 + idx], u0);
        }
    }

    // col sums (pad p contributed 0 via base; pad q lands in ignored slots)
    atomicAdd(&g_colSum[gq + 0], c0);
    atomicAdd(&g_colSum[gq + 1], c1);
    atomicAdd(&g_colSum[gq + 2], c2);
    atomicAdd(&g_colSum[gq + 3], c3);

    // --- last-block finalize (ticket) ---
    __syncthreads();
    __shared__ unsigned int s_last;
    if (tid == 0) {
        __threadfence();
        s_last = (atomicAdd(&g_done, 1u) == (unsigned)(NBLOCKS - 1)) ? 1u : 0u;
    }
    __syncthreads();
    if (s_last) {
        __threadfence();
        float s = 0.f;
        for (int p = tid; p < P2; p += 256)
            s += 30.0f + 0.5f * (logf(g_rowSum[p]) + logf(g_colSum[p])) - g_diag[p];
        s = warp_sum(s);
        if ((tid & 31) == 0) red[tid >> 5] = s;
        __syncthreads();
        if (tid == 0) {
            float tot = 0.f;
            #pragma unroll
            for (int k = 0; k < 8; ++k) tot += red[k];
            out[0] = tot / (float)P2;
        }
    }
}

extern "C" void kernel_launch(void* const* d_in, const int* in_sizes, int n_in,
                              void* d_out, int out_size) {
    const float* txtf = (const float*)d_in[0];
    const float* imgf = (const float*)d_in[1];
    (void)in_sizes; (void)n_in; (void)out_size;
    float* out = (float*)d_out;

    const int smem = (NN * QBLK + PBLK * 3 + 8) * 4;   // ~55.3 KB
    static int configured = 0;
    if (!configured) {
        cudaFuncSetAttribute(lse_main, cudaFuncAttributeMaxDynamicSharedMemorySize, smem);
        configured = 1;
    }

    prep_kernel<<<NGRAMB + NMETAB, 256>>>(txtf, imgf);
    lse_main<<<dim3(GQ, GP), 256, smem>>>(out);
}